// round 13
// baseline (speedup 1.0000x reference)
#include <cuda_runtime.h>
#include <cuda_bf16.h>

#define NB 32
#define NP 32768
#define NC 81
#define NANCH (NB * NP)
#define TPB 128
#define WARPS 4
#define ROWS 4                           // rows per tile (per warp)
#define NBUF 3
#define WTILES 64                        // tiles per warp -> 256 anchors/warp
#define APB (WARPS * ROWS * WTILES)      // 1024 anchors per block
#define GRID (NANCH / APB)               // 1024 blocks, 32 per batch
#define TILE_FLOATS (ROWS * NC)          // 324
#define TILE_BYTES (TILE_FLOATS * 4)     // 1296
#define TILE_F4 (TILE_FLOATS / 4)        // 81
#define WARP_SMEM (NBUF * TILE_FLOATS)   // 972 floats per warp
#define NWSLOT (GRID * WARPS)            // 4096 per-warp partial slots
#define PTPB 1024
#define H14 16384                        // 14-bit digit1 bins
#define PSMEM (H14 * 4)                  // 64KB dynamic smem for post

// -------- scratch (device globals; zero-initialized at module load) --------
__device__ float  g_lossc[NANCH];         // mining scores (0 for pos/ignored)
__device__ double g_part_lossl[NWSLOT];   // per-warp smooth-L1 partials (plain ST)
__device__ double g_part_cepos[NWSLOT];   // per-warp CE-over-positives partials
__device__ int    g_numpos[NB];           // per-batch positive counts
__device__ int    g_hist14[NB * H14];     // per-batch 14-bit (bits[31:18]) histogram (2MB)
__device__ double g_conf_neg;             // CE sum over mined negatives
__device__ unsigned g_done;               // global completion counter

__device__ __forceinline__ unsigned smem_u32(const void* p) {
    return (unsigned)__cvta_generic_to_shared(p);
}
__device__ __forceinline__ void cp16cg(unsigned dst, const void* src) {
    asm volatile("cp.async.cg.shared.global [%0], [%1], 16;\n" :: "r"(dst), "l"(src));
}
#define CP_COMMIT() asm volatile("cp.async.commit_group;\n" ::: "memory")
#define CP_WAIT1()  asm volatile("cp.async.wait_group 1;\n" ::: "memory")

// ============ main: per-warp cp.async.cg pipelines, 14 blocks/SM (unchanged core) ============
__global__ void __launch_bounds__(TPB, 14) mb_main_kernel(
    const float* __restrict__ loc_t, const float* __restrict__ loc_data,
    const int* __restrict__ conf_t, const float* __restrict__ conf_data)
{
    __shared__ float smem[WARPS * WARP_SMEM];   // 15552 B

    const int tid  = threadIdx.x;
    const int w    = tid >> 5;
    const int lane = tid & 31;
    const int q    = lane & 7;               // eighth-row worker (8 lanes per row)
    const int row  = lane >> 3;              // 0..3
    const size_t wbase = (size_t)blockIdx.x * APB + (size_t)w * (ROWS * WTILES);
    float* const wsm = smem + w * WARP_SMEM;
    const unsigned sbase = smem_u32(wsm);
    const int hbase = (blockIdx.x >> 5) << 14;   // batch * 16384

    auto stage = [&](int t, int buf) {
        const float4* __restrict__ src =
            (const float4*)(conf_data) + (((size_t)(wbase + (size_t)t * ROWS) * NC) >> 2);
        const unsigned dst = sbase + (unsigned)buf * TILE_BYTES;
        #pragma unroll
        for (int j = 0; j < 2; j++)
            cp16cg(dst + (unsigned)(lane + j * 32) * 16u, src + lane + j * 32);
        if (lane < TILE_F4 - 64)             // remainder: 17 float4
            cp16cg(dst + (unsigned)(lane + 64) * 16u, src + lane + 64);
    };

    stage(0, 0); CP_COMMIT();
    stage(1, 1); CP_COMMIT();

    float ll = 0.f, ce = 0.f;
    int   np = 0;
    int   cbuf = 0, sbuf = 2;

    for (int t = 0; t < WTILES; t++) {
        CP_WAIT1();
        __syncwarp();
        if (t + 2 < WTILES) stage(t + 2, sbuf);
        CP_COMMIT();
        sbuf = (sbuf == NBUF - 1) ? 0 : sbuf + 1;

        const float* __restrict__ r = wsm + cbuf * TILE_FLOATS + row * NC;
        cbuf = (cbuf == NBUF - 1) ? 0 : cbuf + 1;

        float s0 = 0.f, s1 = 0.f;
        #pragma unroll
        for (int i = 0; i < 10; i += 2) {
            s0 += __expf(r[q * 10 + i]);
            s1 += __expf(r[q * 10 + i + 1]);
        }
        float s = s0 + s1;
        if (q == 7) s += __expf(r[80]);
        s += __shfl_xor_sync(0xffffffffu, s, 1);
        s += __shfl_xor_sync(0xffffffffu, s, 2);
        s += __shfl_xor_sync(0xffffffffu, s, 4);

        if (q == 0) {
            const size_t anchor = wbase + (size_t)t * ROWS + row;
            const int traw = __ldg(&conf_t[anchor]);
            const int tgt  = traw < 0 ? 0 : traw;
            const float val = __logf(s) - r[tgt];          // cross-entropy

            const float stv = (traw == 0) ? fmaxf(val, 0.f) : 0.f;
            g_lossc[anchor] = stv;

            // fused radix digit 1: 14-bit histogram (4 active lanes, warp-aggregated)
            const unsigned bin = __float_as_uint(stv) >> 18;
            const unsigned peers = __match_any_sync(0x01010101u, bin);
            if (lane == __ffs(peers) - 1)
                atomicAdd(&g_hist14[hbase + (int)bin], __popc(peers));

            if (traw > 0) {
                float4 a = ((const float4*)loc_data)[anchor];
                float4 bb = ((const float4*)loc_t)[anchor];
                float d0 = fabsf(a.x - bb.x), d1 = fabsf(a.y - bb.y);
                float d2 = fabsf(a.z - bb.z), d3 = fabsf(a.w - bb.w);
                float sl1;
                sl1  = (d0 < 1.f) ? 0.5f * d0 * d0 : d0 - 0.5f;
                sl1 += (d1 < 1.f) ? 0.5f * d1 * d1 : d1 - 0.5f;
                sl1 += (d2 < 1.f) ? 0.5f * d2 * d2 : d2 - 0.5f;
                sl1 += (d3 < 1.f) ? 0.5f * d3 * d3 : d3 - 0.5f;
                ll += sl1; ce += val; np++;
            }
        }
    }

    #pragma unroll
    for (int o = 16; o; o >>= 1) {
        ll += __shfl_xor_sync(0xffffffffu, ll, o);
        ce += __shfl_xor_sync(0xffffffffu, ce, o);
        np += __shfl_xor_sync(0xffffffffu, np, o);
    }
    if (lane == 0) {
        const int slot = blockIdx.x * WARPS + w;
        g_part_lossl[slot] = (double)ll;
        g_part_cepos[slot] = (double)ce;
        if (np) atomicAdd(&g_numpos[blockIdx.x >> 5], np);
    }
}

// ============ post: 14-bit digit1 staged in smem; tiny boundary bin ============
__global__ void __launch_bounds__(PTPB) mb_post_kernel(float* __restrict__ out) {
    const int b = blockIdx.x;
    const int tid = threadIdx.x, lane = tid & 31, wid = tid >> 5;

    extern __shared__ int smbuf[];             // 64KB dynamic
    int*   const hist14 = smbuf;               // [16384] phase 1
    int*   const hist   = smbuf;               // [4096]  phase 2+ (reuse)
    float* const fsum   = (float*)(smbuf + 4096);

    __shared__ int   wtot[32];
    __shared__ float wsf[32];
    __shared__ int   s_bin, s_krem;

    const int np = g_numpos[b];
    const int k  = min(3 * np, NP - 1);
    int* __restrict__ gh = g_hist14 + ((size_t)b << 14);

    if (k > 0) {
        // ---- phase 1: stage 16K bins into smem; parallel suffix-find bin14 ----
        {
            const int4* __restrict__ gh4 = (const int4*)gh;
            int part = 0;
            #pragma unroll
            for (int j = 0; j < 4; j++) {
                const int4 v = __ldg(&gh4[tid * 4 + j]);
                ((int4*)hist14)[tid * 4 + j] = v;
                part += v.x + v.y + v.z + v.w;
            }
            int ssum = part;
            #pragma unroll
            for (int o = 1; o < 32; o <<= 1) {
                const int v = __shfl_down_sync(0xffffffffu, ssum, o);
                if (lane + o < 32) ssum += v;
            }
            if (lane == 0) wtot[wid] = ssum;
            __syncthreads();
            int hi = 0;
            #pragma unroll
            for (int i = 0; i < 32; i++) if (i > wid) hi += wtot[i];
            const int S_excl = (ssum - part) + hi;
            if (S_excl < k && S_excl + part >= k) {   // exactly one thread crosses
                int krem = k - S_excl;
                int j = 15;
                for (;;) { const int c = hist14[tid * 16 + j];
                           if (c >= krem) break; krem -= c; j--; }
                s_bin = tid * 16 + j; s_krem = krem;
            }
            __syncthreads();
        }
        const unsigned bin14 = (unsigned)s_bin;
        const int krem = s_krem;

        // reset this batch's global hist for next replay; re-init smem for phase 2
        {
            const int4 z = {0, 0, 0, 0};
            #pragma unroll
            for (int j = 0; j < 4; j++) ((int4*)gh)[tid * 4 + j] = z;
        }
        __syncthreads();   // everyone done reading hist14 before reuse
        #pragma unroll
        for (int j = 0; j < 4; j++) { hist[tid * 4 + j] = 0; fsum[tid * 4 + j] = 0.f; }
        __syncthreads();

        // ---- phase 2: single full-batch scan; atomics only for small boundary bin ----
        const uint4* __restrict__ uv =
            (const uint4*)((const unsigned*)g_lossc + (size_t)b * NP);
        float sHi = 0.f;
        #pragma unroll
        for (int j = 0; j < 8; j++) {
            const uint4 u4 = __ldg(&uv[tid + j * PTPB]);
            const unsigned uu[4] = {u4.x, u4.y, u4.z, u4.w};
            #pragma unroll
            for (int e = 0; e < 4; e++) {
                const unsigned u = uu[e];
                const unsigned d = u >> 18;
                if (d > bin14) sHi += __uint_as_float(u);
                else if (d == bin14) {                // ~5-10% of elements
                    const int bbn = (u >> 6) & 4095;  // bits[17:6]
                    atomicAdd(&hist[bbn], 1);
                    atomicAdd(&fsum[bbn], __uint_as_float(u));
                }
            }
        }
        #pragma unroll
        for (int o = 16; o; o >>= 1) sHi += __shfl_xor_sync(0xffffffffu, sHi, o);
        if (lane == 0) wsf[wid] = sHi;
        __syncthreads();

        // ---- phase 3: find binA among 4096 smem bins (bits[17:6]) ----
        {
            int part = 0;
            #pragma unroll
            for (int j = 0; j < 4; j++) part += hist[tid * 4 + j];
            int ssum = part;
            #pragma unroll
            for (int o = 1; o < 32; o <<= 1) {
                const int v = __shfl_down_sync(0xffffffffu, ssum, o);
                if (lane + o < 32) ssum += v;
            }
            if (lane == 0) wtot[wid] = ssum;
            __syncthreads();
            int hi = 0;
            #pragma unroll
            for (int i = 0; i < 32; i++) if (i > wid) hi += wtot[i];
            const int S_excl = (ssum - part) + hi;
            if (S_excl < krem && S_excl + part >= krem) {
                int kr = krem - S_excl;
                int j = 3;
                for (;;) { const int c = hist[tid * 4 + j]; if (c >= kr) break; kr -= c; j--; }
                s_bin = tid * 4 + j;
            }
            __syncthreads();
        }
        const int binA = s_bin;

        // suffix cnt/sum over smem bins > binA
        int cA = 0; float sA = 0.f;
        #pragma unroll
        for (int j = 0; j < 4; j++) {
            const int i = tid * 4 + j;
            if (i > binA) { cA += hist[i]; sA += fsum[i]; }
        }
        #pragma unroll
        for (int o = 16; o; o >>= 1) {
            cA += __shfl_xor_sync(0xffffffffu, cA, o);
            sA += __shfl_xor_sync(0xffffffffu, sA, o);
        }
        __shared__ int wc2[32]; __shared__ float ws2[32];
        if (lane == 0) { wc2[wid] = cA; ws2[wid] = sA; }
        __syncthreads();
        if (tid == 0) {
            int cnt = 0; float sm = 0.f; float shi = 0.f;
            #pragma unroll
            for (int i = 0; i < 32; i++) { cnt += wc2[i]; sm += ws2[i]; shi += wsf[i]; }
            // 26-bit threshold, midpoint of low 6 bits (residual ~1e-7 rel on ties)
            const unsigned T = (bin14 << 18) | ((unsigned)binA << 6) | 0x20u;
            const double Tf = (double)__uint_as_float(T);
            const int    cntTot = (k - krem) + cnt;
            atomicAdd(&g_conf_neg, (double)shi + (double)sm + (double)(k - cntTot) * Tf);
        }
        __syncthreads();
    } else {
        // still reset this batch's global hist (zero-valued entries were counted)
        const int4 z = {0, 0, 0, 0};
        #pragma unroll
        for (int j = 0; j < 4; j++) ((int4*)gh)[tid * 4 + j] = z;
    }

    // ---- global done counter: last of 32 blocks finalizes + resets ----
    __shared__ int s_last;
    if (tid == 0) {
        __threadfence();
        s_last = (atomicAdd(&g_done, 1u) == (unsigned)(NB - 1)) ? 1 : 0;
    }
    __syncthreads();
    if (!s_last) return;
    __threadfence();

    __shared__ double fll[32], fce[32];
    double a = 0.0, c = 0.0;
    #pragma unroll
    for (int j = 0; j < NWSLOT / PTPB; j++) {
        a += g_part_lossl[tid + j * PTPB];
        c += g_part_cepos[tid + j * PTPB];
    }
    #pragma unroll
    for (int o = 16; o; o >>= 1) {
        a += __shfl_xor_sync(0xffffffffu, a, o);
        c += __shfl_xor_sync(0xffffffffu, c, o);
    }
    if (lane == 0) { fll[wid] = a; fce[wid] = c; }
    __syncthreads();
    if (tid == 0) {
        double ll = 0.0, ce = 0.0;
        #pragma unroll
        for (int i = 0; i < 32; i++) { ll += fll[i]; ce += fce[i]; }
        int N = 0;
        for (int i = 0; i < NB; i++) N += g_numpos[i];
        const double Nd = (double)N;
        out[0] = (float)(ll / Nd);
        out[1] = (float)((ce + g_conf_neg) / Nd);
        g_conf_neg = 0.0; g_done = 0u;
    }
    if (tid < NB) g_numpos[tid] = 0;
}

extern "C" void kernel_launch(void* const* d_in, const int* in_sizes, int n_in,
                              void* d_out, int out_size) {
    const float* loc_t = nullptr;
    const float* loc_data = nullptr;
    const int*   conf_t = nullptr;
    const float* conf_data = nullptr;
    for (int i = 0; i < n_in; i++) {
        if (in_sizes[i] == NANCH * NC)      conf_data = (const float*)d_in[i];
        else if (in_sizes[i] == NANCH)      conf_t    = (const int*)d_in[i];
        else if (in_sizes[i] == NANCH * 4) {
            if (!loc_t) loc_t = (const float*)d_in[i];
            else        loc_data = (const float*)d_in[i];
        }
    }

    static bool attr_set = false;
    if (!attr_set) {
        cudaFuncSetAttribute(mb_main_kernel,
                             cudaFuncAttributePreferredSharedMemoryCarveout, 100);
        cudaFuncSetAttribute(mb_post_kernel,
                             cudaFuncAttributeMaxDynamicSharedMemorySize, PSMEM);
        attr_set = true;
    }

    mb_main_kernel<<<GRID, TPB>>>(loc_t, loc_data, conf_t, conf_data);
    mb_post_kernel<<<NB, PTPB, PSMEM>>>((float*)d_out);
}

// round 14
// speedup vs baseline: 1.1249x; 1.1249x over previous
#include <cuda_runtime.h>
#include <cuda_bf16.h>

#define NB 32
#define NP 32768
#define NC 81
#define NANCH (NB * NP)
#define TPB 128
#define WARPS 4
#define ROWS 4                           // rows per tile (per warp)
#define NBUF 3
#define WTILES 64                        // tiles per warp -> 256 anchors/warp
#define APB (WARPS * ROWS * WTILES)      // 1024 anchors per block
#define GRID (NANCH / APB)               // 1024 blocks, 32 per batch
#define TILE_FLOATS (ROWS * NC)          // 324
#define TILE_BYTES (TILE_FLOATS * 4)     // 1296
#define TILE_F4 (TILE_FLOATS / 4)        // 81
#define WARP_SMEM (NBUF * TILE_FLOATS)   // 972 floats per warp
#define NWSLOT (GRID * WARPS)            // 4096 per-warp partial slots
#define PTPB 1024
#define QCAP 6144                        // boundary-element queue capacity
#define PSMEM (4096 * 8 + QCAP * 4)      // hist+fsum+queue = 56KB dynamic

// -------- scratch (device globals; zero-initialized at module load) --------
__device__ float  g_lossc[NANCH];         // mining scores (0 for pos/ignored)
__device__ double g_part_lossl[NWSLOT];   // per-warp smooth-L1 partials (plain ST)
__device__ double g_part_cepos[NWSLOT];   // per-warp CE-over-positives partials
__device__ int    g_numpos[NB];           // per-batch positive counts
__device__ int    g_hist12[NB * 4096];    // per-batch 12-bit (bits[31:20]) histogram
__device__ double g_conf_neg;             // CE sum over mined negatives
__device__ unsigned g_done;               // global completion counter

__device__ __forceinline__ unsigned smem_u32(const void* p) {
    return (unsigned)__cvta_generic_to_shared(p);
}
__device__ __forceinline__ void cp16cg(unsigned dst, const void* src) {
    asm volatile("cp.async.cg.shared.global [%0], [%1], 16;\n" :: "r"(dst), "l"(src));
}
#define CP_COMMIT() asm volatile("cp.async.commit_group;\n" ::: "memory")
#define CP_WAIT1()  asm volatile("cp.async.wait_group 1;\n" ::: "memory")

// ============ main: per-warp cp.async.cg pipelines, 14 blocks/SM (R12 exact) ============
__global__ void __launch_bounds__(TPB, 14) mb_main_kernel(
    const float* __restrict__ loc_t, const float* __restrict__ loc_data,
    const int* __restrict__ conf_t, const float* __restrict__ conf_data)
{
    __shared__ float smem[WARPS * WARP_SMEM];   // 15552 B

    const int tid  = threadIdx.x;
    const int w    = tid >> 5;
    const int lane = tid & 31;
    const int q    = lane & 7;               // eighth-row worker (8 lanes per row)
    const int row  = lane >> 3;              // 0..3
    const size_t wbase = (size_t)blockIdx.x * APB + (size_t)w * (ROWS * WTILES);
    float* const wsm = smem + w * WARP_SMEM;
    const unsigned sbase = smem_u32(wsm);
    const int hbase = (blockIdx.x >> 5) << 12;   // batch * 4096

    auto stage = [&](int t, int buf) {
        const float4* __restrict__ src =
            (const float4*)(conf_data) + (((size_t)(wbase + (size_t)t * ROWS) * NC) >> 2);
        const unsigned dst = sbase + (unsigned)buf * TILE_BYTES;
        #pragma unroll
        for (int j = 0; j < 2; j++)
            cp16cg(dst + (unsigned)(lane + j * 32) * 16u, src + lane + j * 32);
        if (lane < TILE_F4 - 64)             // remainder: 17 float4
            cp16cg(dst + (unsigned)(lane + 64) * 16u, src + lane + 64);
    };

    stage(0, 0); CP_COMMIT();
    stage(1, 1); CP_COMMIT();

    float ll = 0.f, ce = 0.f;
    int   np = 0;
    int   cbuf = 0, sbuf = 2;

    for (int t = 0; t < WTILES; t++) {
        CP_WAIT1();
        __syncwarp();
        if (t + 2 < WTILES) stage(t + 2, sbuf);
        CP_COMMIT();
        sbuf = (sbuf == NBUF - 1) ? 0 : sbuf + 1;

        const float* __restrict__ r = wsm + cbuf * TILE_FLOATS + row * NC;
        cbuf = (cbuf == NBUF - 1) ? 0 : cbuf + 1;

        float s0 = 0.f, s1 = 0.f;
        #pragma unroll
        for (int i = 0; i < 10; i += 2) {
            s0 += __expf(r[q * 10 + i]);
            s1 += __expf(r[q * 10 + i + 1]);
        }
        float s = s0 + s1;
        if (q == 7) s += __expf(r[80]);
        s += __shfl_xor_sync(0xffffffffu, s, 1);
        s += __shfl_xor_sync(0xffffffffu, s, 2);
        s += __shfl_xor_sync(0xffffffffu, s, 4);

        if (q == 0) {
            const size_t anchor = wbase + (size_t)t * ROWS + row;
            const int traw = __ldg(&conf_t[anchor]);
            const int tgt  = traw < 0 ? 0 : traw;
            const float val = __logf(s) - r[tgt];          // cross-entropy

            const float stv = (traw == 0) ? fmaxf(val, 0.f) : 0.f;
            g_lossc[anchor] = stv;

            // fused radix digit 1: 12-bit histogram (4 active lanes, warp-aggregated)
            const unsigned bin = __float_as_uint(stv) >> 20;
            const unsigned peers = __match_any_sync(0x01010101u, bin);
            if (lane == __ffs(peers) - 1)
                atomicAdd(&g_hist12[hbase + (int)bin], __popc(peers));

            if (traw > 0) {
                float4 a = ((const float4*)loc_data)[anchor];
                float4 bb = ((const float4*)loc_t)[anchor];
                float d0 = fabsf(a.x - bb.x), d1 = fabsf(a.y - bb.y);
                float d2 = fabsf(a.z - bb.z), d3 = fabsf(a.w - bb.w);
                float sl1;
                sl1  = (d0 < 1.f) ? 0.5f * d0 * d0 : d0 - 0.5f;
                sl1 += (d1 < 1.f) ? 0.5f * d1 * d1 : d1 - 0.5f;
                sl1 += (d2 < 1.f) ? 0.5f * d2 * d2 : d2 - 0.5f;
                sl1 += (d3 < 1.f) ? 0.5f * d3 * d3 : d3 - 0.5f;
                ll += sl1; ce += val; np++;
            }
        }
    }

    #pragma unroll
    for (int o = 16; o; o >>= 1) {
        ll += __shfl_xor_sync(0xffffffffu, ll, o);
        ce += __shfl_xor_sync(0xffffffffu, ce, o);
        np += __shfl_xor_sync(0xffffffffu, np, o);
    }
    if (lane == 0) {
        const int slot = blockIdx.x * WARPS + w;
        g_part_lossl[slot] = (double)ll;
        g_part_cepos[slot] = (double)ce;
        if (np) atomicAdd(&g_numpos[blockIdx.x >> 5], np);
    }
}

// ============ post: branchless scan + dense boundary queue ============
__global__ void __launch_bounds__(PTPB) mb_post_kernel(float* __restrict__ out) {
    const int b = blockIdx.x;
    const int tid = threadIdx.x, lane = tid & 31, wid = tid >> 5;

    extern __shared__ int smbuf[];
    int*      const hist  = smbuf;                       // [4096]
    float*    const fsum  = (float*)(smbuf + 4096);      // [4096]
    unsigned* const queue = (unsigned*)(smbuf + 8192);   // [QCAP]

    __shared__ int   wtot[32];
    __shared__ float wsf[32];
    __shared__ int   s_bin, s_krem, s_qcnt;

    auto find_bin = [&](int kk, int& out_bin, int& out_krem) {
        int part = 0;
        #pragma unroll
        for (int j = 0; j < 4; j++) part += hist[tid * 4 + j];
        int s = part;
        #pragma unroll
        for (int o = 1; o < 32; o <<= 1) {
            const int v = __shfl_down_sync(0xffffffffu, s, o);
            if (lane + o < 32) s += v;
        }
        if (lane == 0) wtot[wid] = s;
        __syncthreads();
        int hi = 0;
        #pragma unroll
        for (int i = 0; i < 32; i++) if (i > wid) hi += wtot[i];
        const int S_excl = (s - part) + hi;
        if (S_excl < kk && S_excl + part >= kk) {
            int krem = kk - S_excl;
            int j = 3;
            for (;;) { const int c = hist[tid * 4 + j]; if (c >= krem) break; krem -= c; j--; }
            s_bin = tid * 4 + j; s_krem = krem;
        }
        __syncthreads();
        out_bin = s_bin; out_krem = s_krem;
    };

    const int np = g_numpos[b];
    const int k  = min(3 * np, NP - 1);
    int* __restrict__ gh = g_hist12 + (b << 12);

    if (k > 0) {
        // ---- phase 1: find bin12 from fused histogram ----
        #pragma unroll
        for (int j = 0; j < 4; j++) hist[tid * 4 + j] = __ldg(&gh[tid * 4 + j]);
        if (tid == 0) s_qcnt = 0;
        __syncthreads();
        int bin12i, krem;
        find_bin(k, bin12i, krem);
        const unsigned bin12 = (unsigned)bin12i;
        __syncthreads();

        #pragma unroll
        for (int j = 0; j < 4; j++) { hist[tid * 4 + j] = 0; fsum[tid * 4 + j] = 0.f; }
        __syncthreads();

        // ---- phase 2: branchless scan; boundary elements -> dense queue ----
        const uint4* __restrict__ uv =
            (const uint4*)((const unsigned*)g_lossc + (size_t)b * NP);
        float sHi = 0.f;
        #pragma unroll
        for (int j = 0; j < 8; j++) {
            const uint4 u4 = __ldg(&uv[tid + j * PTPB]);
            const unsigned uu[4] = {u4.x, u4.y, u4.z, u4.w};
            #pragma unroll
            for (int e = 0; e < 4; e++) {
                const unsigned u = uu[e];
                const unsigned d = u >> 20;
                sHi += (d > bin12) ? __uint_as_float(u) : 0.f;   // FSEL, no branch
                const bool m = (d == bin12);
                const unsigned mk = __ballot_sync(0xffffffffu, m);
                if (mk) {
                    const int ldr = __ffs(mk) - 1;
                    int base = 0;
                    if (lane == ldr) base = atomicAdd(&s_qcnt, __popc(mk));
                    base = __shfl_sync(0xffffffffu, base, ldr);
                    if (m) {
                        const int idx = base + __popc(mk & ((1u << lane) - 1));
                        if (idx < QCAP) queue[idx] = u;
                        else {   // overflow fallback (rare)
                            atomicAdd(&hist[(u >> 8) & 4095], 1);
                            atomicAdd(&fsum[(u >> 8) & 4095], __uint_as_float(u));
                        }
                    }
                }
            }
        }
        #pragma unroll
        for (int o = 16; o; o >>= 1) sHi += __shfl_xor_sync(0xffffffffu, sHi, o);
        if (lane == 0) wsf[wid] = sHi;
        __syncthreads();

        // ---- phase 2b: dense queue processing (no divergence) ----
        const int qn = min(s_qcnt, QCAP);
        for (int i = tid; i < qn; i += PTPB) {
            const unsigned u = queue[i];
            atomicAdd(&hist[(u >> 8) & 4095], 1);
            atomicAdd(&fsum[(u >> 8) & 4095], __uint_as_float(u));
        }
        __syncthreads();

        // ---- phase 3: find binA among 4096 smem bins (bits[19:8]) ----
        int binA, krem2;
        find_bin(krem, binA, krem2);

        int cA = 0; float sA = 0.f;
        #pragma unroll
        for (int j = 0; j < 4; j++) {
            const int i = tid * 4 + j;
            if (i > binA) { cA += hist[i]; sA += fsum[i]; }
        }
        #pragma unroll
        for (int o = 16; o; o >>= 1) {
            cA += __shfl_xor_sync(0xffffffffu, cA, o);
            sA += __shfl_xor_sync(0xffffffffu, sA, o);
        }
        __shared__ int wc2[32]; __shared__ float ws2[32];
        if (lane == 0) { wc2[wid] = cA; ws2[wid] = sA; }
        __syncthreads();
        if (tid == 0) {
            int cnt = 0; float sm = 0.f; float shi = 0.f;
            #pragma unroll
            for (int i = 0; i < 32; i++) { cnt += wc2[i]; sm += ws2[i]; shi += wsf[i]; }
            const unsigned T = (bin12 << 20) | ((unsigned)binA << 8) | 0x80u;
            const double Tf = (double)__uint_as_float(T);
            const int    cntTot = (k - krem) + cnt;
            atomicAdd(&g_conf_neg, (double)shi + (double)sm + (double)(k - cntTot) * Tf);
        }
        __syncthreads();
    }

    // reset this batch's fused histogram for the next graph replay
    #pragma unroll
    for (int j = 0; j < 4; j++) gh[tid * 4 + j] = 0;

    // ---- global done counter: last of 32 blocks finalizes + resets ----
    __shared__ int s_last;
    if (tid == 0) {
        __threadfence();
        s_last = (atomicAdd(&g_done, 1u) == (unsigned)(NB - 1)) ? 1 : 0;
    }
    __syncthreads();
    if (!s_last) return;
    __threadfence();

    __shared__ double fll[32], fce[32];
    double a = 0.0, c = 0.0;
    #pragma unroll
    for (int j = 0; j < NWSLOT / PTPB; j++) {
        a += g_part_lossl[tid + j * PTPB];
        c += g_part_cepos[tid + j * PTPB];
    }
    #pragma unroll
    for (int o = 16; o; o >>= 1) {
        a += __shfl_xor_sync(0xffffffffu, a, o);
        c += __shfl_xor_sync(0xffffffffu, c, o);
    }
    if (lane == 0) { fll[wid] = a; fce[wid] = c; }
    __syncthreads();
    if (tid == 0) {
        double ll = 0.0, ce = 0.0;
        #pragma unroll
        for (int i = 0; i < 32; i++) { ll += fll[i]; ce += fce[i]; }
        int N = 0;
        for (int i = 0; i < NB; i++) N += g_numpos[i];
        const double Nd = (double)N;
        out[0] = (float)(ll / Nd);
        out[1] = (float)((ce + g_conf_neg) / Nd);
        g_conf_neg = 0.0; g_done = 0u;
    }
    if (tid < NB) g_numpos[tid] = 0;
}

extern "C" void kernel_launch(void* const* d_in, const int* in_sizes, int n_in,
                              void* d_out, int out_size) {
    const float* loc_t = nullptr;
    const float* loc_data = nullptr;
    const int*   conf_t = nullptr;
    const float* conf_data = nullptr;
    for (int i = 0; i < n_in; i++) {
        if (in_sizes[i] == NANCH * NC)      conf_data = (const float*)d_in[i];
        else if (in_sizes[i] == NANCH)      conf_t    = (const int*)d_in[i];
        else if (in_sizes[i] == NANCH * 4) {
            if (!loc_t) loc_t = (const float*)d_in[i];
            else        loc_data = (const float*)d_in[i];
        }
    }

    static bool attr_set = false;
    if (!attr_set) {
        cudaFuncSetAttribute(mb_main_kernel,
                             cudaFuncAttributePreferredSharedMemoryCarveout, 100);
        cudaFuncSetAttribute(mb_post_kernel,
                             cudaFuncAttributeMaxDynamicSharedMemorySize, PSMEM);
        attr_set = true;
    }

    mb_main_kernel<<<GRID, TPB>>>(loc_t, loc_data, conf_t, conf_data);
    mb_post_kernel<<<NB, PTPB, PSMEM>>>((float*)d_out);
}

// round 15
// speedup vs baseline: 1.2180x; 1.0827x over previous
#include <cuda_runtime.h>
#include <cuda_bf16.h>

#define NB 32
#define NP 32768
#define NC 81
#define NANCH (NB * NP)
#define TPB 128
#define WARPS 4
#define ROWS 4                           // rows per tile (per warp)
#define NBUF 3
#define WTILES 64                        // tiles per warp -> 256 anchors/warp
#define APB (WARPS * ROWS * WTILES)      // 1024 anchors per block
#define GRID (NANCH / APB)               // 1024 blocks, 32 per batch
#define TILE_FLOATS (ROWS * NC)          // 324
#define TILE_BYTES (TILE_FLOATS * 4)     // 1296
#define TILE_F4 (TILE_FLOATS / 4)        // 81
#define WARP_SMEM (NBUF * TILE_FLOATS)   // 972 floats per warp
#define NWSLOT (GRID * WARPS)            // 4096 per-warp partial slots
#define PTPB 1024

// -------- scratch (device globals; zero-initialized at module load) --------
__device__ float  g_lossc[NANCH];         // mining scores (0 for pos/ignored)
__device__ double g_part_lossl[NWSLOT];   // per-warp smooth-L1 partials (plain ST)
__device__ double g_part_cepos[NWSLOT];   // per-warp CE-over-positives partials
__device__ int    g_numpos[NB];           // per-batch positive counts
__device__ int    g_hist12[NB * 4096];    // per-batch 12-bit (bits[31:20]) histogram
__device__ double g_conf_neg;             // CE sum over mined negatives
__device__ unsigned g_done;               // global completion counter

__device__ __forceinline__ unsigned smem_u32(const void* p) {
    return (unsigned)__cvta_generic_to_shared(p);
}
__device__ __forceinline__ void cp16cg(unsigned dst, const void* src) {
    asm volatile("cp.async.cg.shared.global [%0], [%1], 16;\n" :: "r"(dst), "l"(src));
}
#define CP_COMMIT() asm volatile("cp.async.commit_group;\n" ::: "memory")
#define CP_WAIT1()  asm volatile("cp.async.wait_group 1;\n" ::: "memory")

// ============ main: per-warp cp.async.cg pipelines, 14 blocks/SM (R12 exact) ============
__global__ void __launch_bounds__(TPB, 14) mb_main_kernel(
    const float* __restrict__ loc_t, const float* __restrict__ loc_data,
    const int* __restrict__ conf_t, const float* __restrict__ conf_data)
{
    __shared__ float smem[WARPS * WARP_SMEM];   // 15552 B

    const int tid  = threadIdx.x;
    const int w    = tid >> 5;
    const int lane = tid & 31;
    const int q    = lane & 7;               // eighth-row worker (8 lanes per row)
    const int row  = lane >> 3;              // 0..3
    const size_t wbase = (size_t)blockIdx.x * APB + (size_t)w * (ROWS * WTILES);
    float* const wsm = smem + w * WARP_SMEM;
    const unsigned sbase = smem_u32(wsm);
    const int hbase = (blockIdx.x >> 5) << 12;   // batch * 4096

    auto stage = [&](int t, int buf) {
        const float4* __restrict__ src =
            (const float4*)(conf_data) + (((size_t)(wbase + (size_t)t * ROWS) * NC) >> 2);
        const unsigned dst = sbase + (unsigned)buf * TILE_BYTES;
        #pragma unroll
        for (int j = 0; j < 2; j++)
            cp16cg(dst + (unsigned)(lane + j * 32) * 16u, src + lane + j * 32);
        if (lane < TILE_F4 - 64)             // remainder: 17 float4
            cp16cg(dst + (unsigned)(lane + 64) * 16u, src + lane + 64);
    };

    stage(0, 0); CP_COMMIT();
    stage(1, 1); CP_COMMIT();

    float ll = 0.f, ce = 0.f;
    int   np = 0;
    int   cbuf = 0, sbuf = 2;

    for (int t = 0; t < WTILES; t++) {
        CP_WAIT1();
        __syncwarp();
        if (t + 2 < WTILES) stage(t + 2, sbuf);
        CP_COMMIT();
        sbuf = (sbuf == NBUF - 1) ? 0 : sbuf + 1;

        const float* __restrict__ r = wsm + cbuf * TILE_FLOATS + row * NC;
        cbuf = (cbuf == NBUF - 1) ? 0 : cbuf + 1;

        float s0 = 0.f, s1 = 0.f;
        #pragma unroll
        for (int i = 0; i < 10; i += 2) {
            s0 += __expf(r[q * 10 + i]);
            s1 += __expf(r[q * 10 + i + 1]);
        }
        float s = s0 + s1;
        if (q == 7) s += __expf(r[80]);
        s += __shfl_xor_sync(0xffffffffu, s, 1);
        s += __shfl_xor_sync(0xffffffffu, s, 2);
        s += __shfl_xor_sync(0xffffffffu, s, 4);

        if (q == 0) {
            const size_t anchor = wbase + (size_t)t * ROWS + row;
            const int traw = __ldg(&conf_t[anchor]);
            const int tgt  = traw < 0 ? 0 : traw;
            const float val = __logf(s) - r[tgt];          // cross-entropy

            const float stv = (traw == 0) ? fmaxf(val, 0.f) : 0.f;
            g_lossc[anchor] = stv;

            // fused radix digit 1: 12-bit histogram (4 active lanes, warp-aggregated)
            const unsigned bin = __float_as_uint(stv) >> 20;
            const unsigned peers = __match_any_sync(0x01010101u, bin);
            if (lane == __ffs(peers) - 1)
                atomicAdd(&g_hist12[hbase + (int)bin], __popc(peers));

            if (traw > 0) {
                float4 a = ((const float4*)loc_data)[anchor];
                float4 bb = ((const float4*)loc_t)[anchor];
                float d0 = fabsf(a.x - bb.x), d1 = fabsf(a.y - bb.y);
                float d2 = fabsf(a.z - bb.z), d3 = fabsf(a.w - bb.w);
                float sl1;
                sl1  = (d0 < 1.f) ? 0.5f * d0 * d0 : d0 - 0.5f;
                sl1 += (d1 < 1.f) ? 0.5f * d1 * d1 : d1 - 0.5f;
                sl1 += (d2 < 1.f) ? 0.5f * d2 * d2 : d2 - 0.5f;
                sl1 += (d3 < 1.f) ? 0.5f * d3 * d3 : d3 - 0.5f;
                ll += sl1; ce += val; np++;
            }
        }
    }

    #pragma unroll
    for (int o = 16; o; o >>= 1) {
        ll += __shfl_xor_sync(0xffffffffu, ll, o);
        ce += __shfl_xor_sync(0xffffffffu, ce, o);
        np += __shfl_xor_sync(0xffffffffu, np, o);
    }
    if (lane == 0) {
        const int slot = blockIdx.x * WARPS + w;
        g_part_lossl[slot] = (double)ll;
        g_part_cepos[slot] = (double)ce;
        if (np) atomicAdd(&g_numpos[blockIdx.x >> 5], np);
    }
}

// ============ post: count-only radix + final branchless threshold sweep ============
__global__ void __launch_bounds__(PTPB) mb_post_kernel(float* __restrict__ out) {
    const int b = blockIdx.x;
    const int tid = threadIdx.x, lane = tid & 31, wid = tid >> 5;

    __shared__ int   hist[4096];
    __shared__ int   wtot[32];
    __shared__ float wsf[32];
    __shared__ int   s_bin;

    // parallel "find bin where descending cumulative count crosses kk" (count-only)
    auto find_bin = [&](int kk) -> int {
        int part = 0;
        #pragma unroll
        for (int j = 0; j < 4; j++) part += hist[tid * 4 + j];
        int s = part;
        #pragma unroll
        for (int o = 1; o < 32; o <<= 1) {
            const int v = __shfl_down_sync(0xffffffffu, s, o);
            if (lane + o < 32) s += v;
        }
        if (lane == 0) wtot[wid] = s;
        __syncthreads();
        int hi = 0;
        #pragma unroll
        for (int i = 0; i < 32; i++) if (i > wid) hi += wtot[i];
        const int S_excl = (s - part) + hi;
        if (S_excl < kk && S_excl + part >= kk) {   // exactly one thread crosses
            int krem = kk - S_excl;
            int j = 3;
            for (;;) { const int c = hist[tid * 4 + j]; if (c >= krem) break; krem -= c; j--; }
            s_bin = tid * 4 + j;
        }
        __syncthreads();
        return s_bin;
    };

    const int np = g_numpos[b];
    const int k  = min(3 * np, NP - 1);
    int* __restrict__ gh = g_hist12 + (b << 12);

    if (k > 0) {
        // ---- phase 1: find bin12 from the fused histogram ----
        #pragma unroll
        for (int j = 0; j < 4; j++) hist[tid * 4 + j] = __ldg(&gh[tid * 4 + j]);
        __syncthreads();
        const unsigned bin12 = (unsigned)find_bin(k);
        __syncthreads();

        #pragma unroll
        for (int j = 0; j < 4; j++) hist[tid * 4 + j] = 0;
        __syncthreads();

        // ---- phase 2: count-only hist of boundary-bin bits[19:8] ----
        const uint4* __restrict__ uv =
            (const uint4*)((const unsigned*)g_lossc + (size_t)b * NP);
        #pragma unroll
        for (int j = 0; j < 8; j++) {
            const uint4 u4 = __ldg(&uv[tid + j * PTPB]);
            const unsigned uu[4] = {u4.x, u4.y, u4.z, u4.w};
            #pragma unroll
            for (int e = 0; e < 4; e++) {
                const unsigned u = uu[e];
                if ((u >> 20) == bin12) atomicAdd(&hist[(u >> 8) & 4095], 1);
            }
        }
        __syncthreads();

        // ---- phase 3: find cumulative count of bins > bin12, then binA ----
        // kk for phase-3 = k minus count of elements with digit > bin12.
        // That count = k - krem, but we avoid tracking krem: elements with
        // d > bin12 all rank above binA. Equivalent: binA = crossing of
        // (k - cnt_above12). Compute cnt_above12 from the staged hist12? It was
        // overwritten — instead recompute from phase-2's complement: total in
        // boundary bin = sum(hist); cnt_above12 = (known) k crossing...
        // Simplest exact route: cnt_above12 via one warp-reduce over gh (still
        // intact in global).
        int cAbove = 0;
        for (int i = tid; i < 4096; i += PTPB)
            if (i > (int)bin12) cAbove += __ldg(&gh[i]);
        #pragma unroll
        for (int o = 16; o; o >>= 1) cAbove += __shfl_xor_sync(0xffffffffu, cAbove, o);
        if (lane == 0) wtot[wid] = cAbove;
        __syncthreads();
        int cnt12 = 0;
        #pragma unroll
        for (int i = 0; i < 32; i++) cnt12 += wtot[i];
        __syncthreads();   // wtot reused inside find_bin

        const int binA = find_bin(k - cnt12);

        // ---- phase 4: branchless sweep, exact cnt/sum of u >= Thi ----
        const unsigned Thi = ((bin12 << 12) | (unsigned)binA) + 1u << 8;   // top edge of binA
        float sum = 0.f; int cnt = 0;
        #pragma unroll
        for (int j = 0; j < 8; j++) {
            const uint4 u4 = __ldg(&uv[tid + j * PTPB]);
            const unsigned uu[4] = {u4.x, u4.y, u4.z, u4.w};
            #pragma unroll
            for (int e = 0; e < 4; e++) {
                const bool g = uu[e] >= Thi;
                sum += g ? __uint_as_float(uu[e]) : 0.f;   // FSEL
                cnt += g;
            }
        }
        #pragma unroll
        for (int o = 16; o; o >>= 1) {
            sum += __shfl_xor_sync(0xffffffffu, sum, o);
            cnt += __shfl_xor_sync(0xffffffffu, cnt, o);
        }
        if (lane == 0) { wsf[wid] = sum; wtot[wid] = cnt; }
        __syncthreads();
        if (tid == 0) {
            float S = 0.f; int C = 0;
            #pragma unroll
            for (int i = 0; i < 32; i++) { S += wsf[i]; C += wtot[i]; }
            // remaining k-C slots filled at binA midpoint (residual ~1e-7 rel)
            const unsigned Tmid = (bin12 << 20) | ((unsigned)binA << 8) | 0x80u;
            const double Tf = (double)__uint_as_float(Tmid);
            atomicAdd(&g_conf_neg, (double)S + (double)(k - C) * Tf);
        }
        __syncthreads();
    }

    // reset this batch's fused histogram for the next graph replay
    #pragma unroll
    for (int j = 0; j < 4; j++) gh[tid * 4 + j] = 0;

    // ---- global done counter: last of 32 blocks finalizes + resets ----
    __shared__ int s_last;
    if (tid == 0) {
        __threadfence();
        s_last = (atomicAdd(&g_done, 1u) == (unsigned)(NB - 1)) ? 1 : 0;
    }
    __syncthreads();
    if (!s_last) return;
    __threadfence();

    __shared__ double fll[32], fce[32];
    double a = 0.0, c = 0.0;
    #pragma unroll
    for (int j = 0; j < NWSLOT / PTPB; j++) {
        a += g_part_lossl[tid + j * PTPB];
        c += g_part_cepos[tid + j * PTPB];
    }
    #pragma unroll
    for (int o = 16; o; o >>= 1) {
        a += __shfl_xor_sync(0xffffffffu, a, o);
        c += __shfl_xor_sync(0xffffffffu, c, o);
    }
    if (lane == 0) { fll[wid] = a; fce[wid] = c; }
    __syncthreads();
    if (tid == 0) {
        double ll = 0.0, ce = 0.0;
        #pragma unroll
        for (int i = 0; i < 32; i++) { ll += fll[i]; ce += fce[i]; }
        int N = 0;
        for (int i = 0; i < NB; i++) N += g_numpos[i];
        const double Nd = (double)N;
        out[0] = (float)(ll / Nd);
        out[1] = (float)((ce + g_conf_neg) / Nd);
        g_conf_neg = 0.0; g_done = 0u;
    }
    if (tid < NB) g_numpos[tid] = 0;
}

extern "C" void kernel_launch(void* const* d_in, const int* in_sizes, int n_in,
                              void* d_out, int out_size) {
    const float* loc_t = nullptr;
    const float* loc_data = nullptr;
    const int*   conf_t = nullptr;
    const float* conf_data = nullptr;
    for (int i = 0; i < n_in; i++) {
        if (in_sizes[i] == NANCH * NC)      conf_data = (const float*)d_in[i];
        else if (in_sizes[i] == NANCH)      conf_t    = (const int*)d_in[i];
        else if (in_sizes[i] == NANCH * 4) {
            if (!loc_t) loc_t = (const float*)d_in[i];
            else        loc_data = (const float*)d_in[i];
        }
    }

    static bool attr_set = false;
    if (!attr_set) {
        cudaFuncSetAttribute(mb_main_kernel,
                             cudaFuncAttributePreferredSharedMemoryCarveout, 100);
        attr_set = true;
    }

    mb_main_kernel<<<GRID, TPB>>>(loc_t, loc_data, conf_t, conf_data);
    mb_post_kernel<<<NB, PTPB>>>((float*)d_out);
}